// round 2
// baseline (speedup 1.0000x reference)
#include <cuda_runtime.h>

#define BATCH 4
#define TT    1024
#define DD    1024
#define HH    8
#define DKK   128
#define PP    2047
#define MHS   (BATCH*TT)

// ---------------- scratch (device globals: no allocations allowed) ----------
__device__ float g_qu[BATCH*HH*TT*DKK];          // 16 MB  (B,H,T,DK)
__device__ float g_qv[BATCH*HH*TT*DKK];          // 16 MB
__device__ float g_k [BATCH*HH*TT*DKK];          // 16 MB
__device__ float g_v [BATCH*HH*TT*DKK];          // 16 MB
__device__ float g_p [HH*PP*DKK];                // 8 MB   (H,P,DK)
__device__ float g_scores[(size_t)BATCH*HH*TT*TT]; // 128 MB (B,H,T,T)
__device__ float g_o [BATCH*TT*DD];              // 16 MB  (B,T,D)

// ---------------- shared NT mainloop: C = A(MxK) * B(NxK)^T, 64x64 tile -----
// 256 threads, 4x4 microtile per thread, BK=16.
__device__ __forceinline__ void nt_mainloop(const float* __restrict__ A,
                                            const float* __restrict__ B,
                                            int M, int N, int K,
                                            int row0, int col0,
                                            float acc[4][4])
{
    __shared__ float As[16][64];
    __shared__ float Bs[16][64];
    const int tid = threadIdx.x;
    const int tx  = tid & 15, ty = tid >> 4;
    const int lr  = tid >> 2;          // 0..63  (row within tile)
    const int lc  = (tid & 3) << 2;    // 0,4,8,12 (k offset, float4)

    for (int k0 = 0; k0 < K; k0 += 16) {
        float4 a4 = {0.f,0.f,0.f,0.f}, b4 = {0.f,0.f,0.f,0.f};
        int ar = row0 + lr;
        if (ar < M) a4 = *reinterpret_cast<const float4*>(&A[(size_t)ar*K + k0 + lc]);
        int br = col0 + lr;
        if (br < N) b4 = *reinterpret_cast<const float4*>(&B[(size_t)br*K + k0 + lc]);
        As[lc+0][lr] = a4.x; As[lc+1][lr] = a4.y; As[lc+2][lr] = a4.z; As[lc+3][lr] = a4.w;
        Bs[lc+0][lr] = b4.x; Bs[lc+1][lr] = b4.y; Bs[lc+2][lr] = b4.z; Bs[lc+3][lr] = b4.w;
        __syncthreads();
        #pragma unroll
        for (int kk = 0; kk < 16; kk++) {
            float4 av = *reinterpret_cast<const float4*>(&As[kk][ty << 2]);
            float4 bv = *reinterpret_cast<const float4*>(&Bs[kk][tx << 2]);
            float ar_[4] = {av.x, av.y, av.z, av.w};
            float br_[4] = {bv.x, bv.y, bv.z, bv.w};
            #pragma unroll
            for (int i = 0; i < 4; i++)
                #pragma unroll
                for (int j = 0; j < 4; j++)
                    acc[i][j] += ar_[i] * br_[j];
        }
        __syncthreads();
    }
}

// ---------------- Q/K/V projection: hs(4096x1024) @ W^T, fused bias adds ----
__global__ void k_qkv(const float* __restrict__ hs,
                      const float* __restrict__ Wq,
                      const float* __restrict__ Wk,
                      const float* __restrict__ Wv,
                      const float* __restrict__ bu,
                      const float* __restrict__ bv)
{
    const float* W = (blockIdx.z == 0) ? Wq : ((blockIdx.z == 1) ? Wk : Wv);
    const int row0 = blockIdx.y * 64, col0 = blockIdx.x * 64;
    float acc[4][4] = {};
    nt_mainloop(hs, W, MHS, DD, DD, row0, col0, acc);
    const int tx = threadIdx.x & 15, ty = threadIdx.x >> 4;
    #pragma unroll
    for (int i = 0; i < 4; i++) {
        int m = row0 + (ty << 2) + i;
        int b = m >> 10, t = m & 1023;
        #pragma unroll
        for (int j = 0; j < 4; j++) {
            int n = col0 + (tx << 2) + j;
            int h = n >> 7, d = n & 127;
            size_t idx = ((size_t)(b * HH + h) * TT + t) * DKK + d;
            float a = acc[i][j];
            if (blockIdx.z == 0) {
                g_qu[idx] = a + bu[h * DKK + d];
                g_qv[idx] = a + bv[h * DKK + d];
            } else if (blockIdx.z == 1) {
                g_k[idx] = a;
            } else {
                g_v[idx] = a;
            }
        }
    }
}

// ---------------- P projection: pos_emb(2047x1024) @ Wp^T -> (H,P,DK) -------
__global__ void k_p(const float* __restrict__ pe, const float* __restrict__ Wp)
{
    const int row0 = blockIdx.y * 64, col0 = blockIdx.x * 64;
    float acc[4][4] = {};
    nt_mainloop(pe, Wp, PP, DD, DD, row0, col0, acc);
    const int tx = threadIdx.x & 15, ty = threadIdx.x >> 4;
    #pragma unroll
    for (int i = 0; i < 4; i++) {
        int m = row0 + (ty << 2) + i;
        if (m >= PP) continue;
        #pragma unroll
        for (int j = 0; j < 4; j++) {
            int n = col0 + (tx << 2) + j;
            int h = n >> 7, d = n & 127;
            g_p[((size_t)h * PP + m) * DKK + d] = acc[i][j];
        }
    }
}

// ---------------- AC: scores = qu @ k^T per (b,h) ---------------------------
__global__ void k_ac()
{
    const int bh = blockIdx.z;
    const float* A  = g_qu + (size_t)bh * TT * DKK;
    const float* Bm = g_k  + (size_t)bh * TT * DKK;
    float* C = g_scores + (size_t)bh * TT * TT;
    const int row0 = blockIdx.y * 64, col0 = blockIdx.x * 64;
    float acc[4][4] = {};
    nt_mainloop(A, Bm, TT, TT, DKK, row0, col0, acc);
    const int tx = threadIdx.x & 15, ty = threadIdx.x >> 4;
    #pragma unroll
    for (int i = 0; i < 4; i++) {
        int m = row0 + (ty << 2) + i;
        #pragma unroll
        for (int j = 0; j < 4; j++) {
            int n = col0 + (tx << 2) + j;
            C[(size_t)m * TT + n] = acc[i][j];
        }
    }
}

// ---------------- BD: scores[m, n+m-1023] += qv @ p^T (rel-shift fused) -----
__global__ void k_bd()
{
    const int bh = blockIdx.z, h = bh & 7;
    const int row0 = blockIdx.y * 64, col0 = blockIdx.x * 64;
    // tile entirely out of the shifted window? (k = n + m - 1023, need 0<=k<T)
    if (row0 + col0 + 126 < 1023 || row0 + col0 > 2046) return;
    const float* A  = g_qv + (size_t)bh * TT * DKK;
    const float* Bm = g_p  + (size_t)h * PP * DKK;
    float* C = g_scores + (size_t)bh * TT * TT;
    float acc[4][4] = {};
    nt_mainloop(A, Bm, TT, PP, DKK, row0, col0, acc);
    const int tx = threadIdx.x & 15, ty = threadIdx.x >> 4;
    #pragma unroll
    for (int i = 0; i < 4; i++) {
        int m = row0 + (ty << 2) + i;
        #pragma unroll
        for (int j = 0; j < 4; j++) {
            int n = col0 + (tx << 2) + j;
            if (n < PP) {
                int k = n + m - 1023;
                if (k >= 0 && k < TT)
                    C[(size_t)m * TT + k] += acc[i][j];
            }
        }
    }
}

// ---------------- softmax over each length-1024 row (with 1/sqrt(dk)) -------
__global__ void k_softmax()
{
    float* r = g_scores + (size_t)blockIdx.x * TT;
    const int tid = threadIdx.x;                 // 256 threads, float4 each
    float4 v = reinterpret_cast<float4*>(r)[tid];
    const float s = 0.08838834764831845f;        // 1/sqrt(128)
    v.x *= s; v.y *= s; v.z *= s; v.w *= s;

    __shared__ float redm[8];
    __shared__ float reds[8];

    float m = fmaxf(fmaxf(v.x, v.y), fmaxf(v.z, v.w));
    #pragma unroll
    for (int o = 16; o > 0; o >>= 1) m = fmaxf(m, __shfl_xor_sync(~0u, m, o));
    if ((tid & 31) == 0) redm[tid >> 5] = m;
    __syncthreads();
    m = redm[0];
    #pragma unroll
    for (int w = 1; w < 8; w++) m = fmaxf(m, redm[w]);

    float4 e;
    e.x = __expf(v.x - m); e.y = __expf(v.y - m);
    e.z = __expf(v.z - m); e.w = __expf(v.w - m);
    float sum = e.x + e.y + e.z + e.w;
    #pragma unroll
    for (int o = 16; o > 0; o >>= 1) sum += __shfl_xor_sync(~0u, sum, o);
    if ((tid & 31) == 0) reds[tid >> 5] = sum;
    __syncthreads();
    sum = reds[0];
    #pragma unroll
    for (int w = 1; w < 8; w++) sum += reds[w];

    float inv = __frcp_rn(sum);
    e.x *= inv; e.y *= inv; e.z *= inv; e.w *= inv;
    reinterpret_cast<float4*>(r)[tid] = e;
}

// ---------------- AV: o = attn(1024x1024) @ v(1024x128) per (b,h), NN -------
__global__ void k_av()
{
    const int bh = blockIdx.z, b = bh >> 3, h = bh & 7;
    const float* A  = g_scores + (size_t)bh * TT * TT;
    const float* Bm = g_v      + (size_t)bh * TT * DKK;
    const int row0 = blockIdx.y * 64, col0 = blockIdx.x * 64;

    __shared__ float As[16][64];
    __shared__ float Bs[16][64];
    const int tid = threadIdx.x;
    const int tx = tid & 15, ty = tid >> 4;
    const int lr = tid >> 2, lc = (tid & 3) << 2;    // A tile: 64 rows x 16 k
    const int br_ = tid >> 4, bc = (tid & 15) << 2;  // B tile: 16 k x 64 n
    float acc[4][4] = {};

    for (int k0 = 0; k0 < TT; k0 += 16) {
        float4 a4 = *reinterpret_cast<const float4*>(&A[(size_t)(row0 + lr) * TT + k0 + lc]);
        As[lc+0][lr] = a4.x; As[lc+1][lr] = a4.y; As[lc+2][lr] = a4.z; As[lc+3][lr] = a4.w;
        float4 b4 = *reinterpret_cast<const float4*>(&Bm[(size_t)(k0 + br_) * DKK + col0 + bc]);
        *reinterpret_cast<float4*>(&Bs[br_][bc]) = b4;
        __syncthreads();
        #pragma unroll
        for (int kk = 0; kk < 16; kk++) {
            float4 av = *reinterpret_cast<const float4*>(&As[kk][ty << 2]);
            float4 bv = *reinterpret_cast<const float4*>(&Bs[kk][tx << 2]);
            float ar_[4] = {av.x, av.y, av.z, av.w};
            float br2[4] = {bv.x, bv.y, bv.z, bv.w};
            #pragma unroll
            for (int i = 0; i < 4; i++)
                #pragma unroll
                for (int j = 0; j < 4; j++)
                    acc[i][j] += ar_[i] * br2[j];
        }
        __syncthreads();
    }
    #pragma unroll
    for (int i = 0; i < 4; i++) {
        int m = row0 + (ty << 2) + i;
        #pragma unroll
        for (int j = 0; j < 4; j++) {
            int n = col0 + (tx << 2) + j;
            g_o[(((size_t)b * TT + m) * HH + h) * DKK + n] = acc[i][j];
        }
    }
}

// ---------------- output projection: o(4096x1024) @ Wo^T -> d_out -----------
__global__ void k_out(const float* __restrict__ Wo, float* __restrict__ out)
{
    const int row0 = blockIdx.y * 64, col0 = blockIdx.x * 64;
    float acc[4][4] = {};
    nt_mainloop(g_o, Wo, MHS, DD, DD, row0, col0, acc);
    const int tx = threadIdx.x & 15, ty = threadIdx.x >> 4;
    #pragma unroll
    for (int i = 0; i < 4; i++) {
        int m = row0 + (ty << 2) + i;
        #pragma unroll
        for (int j = 0; j < 4; j++) {
            int n = col0 + (tx << 2) + j;
            out[(size_t)m * DD + n] = acc[i][j];
        }
    }
}

// ---------------- launch ----------------------------------------------------
extern "C" void kernel_launch(void* const* d_in, const int* in_sizes, int n_in,
                              void* d_out, int out_size)
{
    const float* hs = (const float*)d_in[0];
    const float* pe = (const float*)d_in[1];
    const float* Wq = (const float*)d_in[2];
    const float* Wk = (const float*)d_in[3];
    const float* Wv = (const float*)d_in[4];
    const float* Wo = (const float*)d_in[5];
    const float* Wp = (const float*)d_in[6];
    const float* bu = (const float*)d_in[7];
    const float* bv = (const float*)d_in[8];
    float* out = (float*)d_out;

    k_qkv<<<dim3(16, 64, 3), 256>>>(hs, Wq, Wk, Wv, bu, bv);
    k_p  <<<dim3(16, 32), 256>>>(pe, Wp);
    k_ac <<<dim3(16, 16, BATCH * HH), 256>>>();
    k_bd <<<dim3(32, 16, BATCH * HH), 256>>>();
    k_softmax<<<BATCH * HH * TT, 256>>>();
    k_av <<<dim3(2, 16, BATCH * HH), 256>>>();
    k_out<<<dim3(16, 64), 256>>>(Wo, out);
}

// round 3
// speedup vs baseline: 1.4700x; 1.4700x over previous
#include <cuda_runtime.h>
#include <cuda_bf16.h>

#define BATCH 4
#define TT    1024
#define DD    1024
#define HH    8
#define DKK   128
#define PP    2047
#define MHS   (BATCH*TT)
#define BK    32
#define BKP   40   // padded smem row (halves): conflict-free fragment banks

// ---------------- scratch (device globals; ushort = raw bf16) ---------------
__device__ unsigned short g_hshi[MHS*DD],  g_hslo[MHS*DD];
__device__ unsigned short g_pehi[PP*DD],   g_pelo[PP*DD];
__device__ unsigned short g_Wqhi[DD*DD],   g_Wqlo[DD*DD];
__device__ unsigned short g_Wkhi[DD*DD],   g_Wklo[DD*DD];
__device__ unsigned short g_Wvhi[DD*DD],   g_Wvlo[DD*DD];
__device__ unsigned short g_Wohi[DD*DD],   g_Wolo[DD*DD];
__device__ unsigned short g_Wphi[DD*DD],   g_Wplo[DD*DD];
__device__ unsigned short g_quhi[BATCH*HH*TT*DKK], g_qulo[BATCH*HH*TT*DKK];
__device__ unsigned short g_qvhi[BATCH*HH*TT*DKK], g_qvlo[BATCH*HH*TT*DKK];
__device__ unsigned short g_khi [BATCH*HH*TT*DKK], g_klo [BATCH*HH*TT*DKK];
__device__ unsigned short g_vThi[BATCH*HH*DKK*TT], g_vTlo[BATCH*HH*DKK*TT]; // (b,h,d,t)
__device__ unsigned short g_phi [HH*PP*DKK],       g_plo [HH*PP*DKK];
__device__ unsigned short g_athi[(size_t)BATCH*HH*TT*TT], g_atlo[(size_t)BATCH*HH*TT*TT];
__device__ unsigned short g_ohi [MHS*DD],  g_olo [MHS*DD];
__device__ float g_scores[(size_t)BATCH*HH*TT*TT]; // 134 MB fp32

typedef const __nv_bfloat16* bfp;

// ---------------- helpers ---------------------------------------------------
__device__ __forceinline__ void split2(float x, unsigned short& h, unsigned short& l)
{
    __nv_bfloat16 hb = __float2bfloat16_rn(x);
    float hf = __bfloat162float(hb);
    __nv_bfloat16 lb = __float2bfloat16_rn(x - hf);
    h = __bfloat16_as_ushort(hb);
    l = __bfloat16_as_ushort(lb);
}

#define MMA_BF16(D, A, B0, B1)                                             \
    asm volatile("mma.sync.aligned.m16n8k16.row.col.f32.bf16.bf16.f32 "    \
                 "{%0,%1,%2,%3}, {%4,%5,%6,%7}, {%8,%9}, {%0,%1,%2,%3};"   \
                 : "+f"(D[0]), "+f"(D[1]), "+f"(D[2]), "+f"(D[3])          \
                 : "r"(A[0]), "r"(A[1]), "r"(A[2]), "r"(A[3]),             \
                   "r"(B0), "r"(B1))

// ---------------- split-precision NT mainloop: C = A(MxK)*B(NxK)^T ----------
// 128x128 block tile, 256 threads (8 warps, each 32x64), BK=32.
// hi*hi + hi*lo + lo*hi (lo*lo dropped, ~2^-16 relative).
__device__ __forceinline__ void bmma_main(
    bfp Ahi, bfp Alo, int M,
    bfp Bhi, bfp Blo, int N,
    int K, int row0, int col0, float acc[2][8][4])
{
    __shared__ __align__(16) __nv_bfloat16 sAh[128][BKP];
    __shared__ __align__(16) __nv_bfloat16 sAl[128][BKP];
    __shared__ __align__(16) __nv_bfloat16 sBh[128][BKP];
    __shared__ __align__(16) __nv_bfloat16 sBl[128][BKP];

    const int tid  = threadIdx.x;
    const int lane = tid & 31, warp = tid >> 5;
    const int grp  = lane >> 2, qid = lane & 3;
    const int wm   = warp >> 1, wn = warp & 1;
    const int lr   = tid >> 2;       // 0..63 (tile row for loads)
    const int seg  = tid & 3;        // 8-half segment within BK

    for (int k0 = 0; k0 < K; k0 += BK) {
        #pragma unroll
        for (int half = 0; half < 2; half++) {
            int r  = lr + half * 64;
            int gk = k0 + seg * 8;
            uint4 z4 = make_uint4(0u, 0u, 0u, 0u);
            uint4 vah = z4, valo = z4, vbh = z4, vblo = z4;
            int ga = row0 + r;
            if (ga < M) {
                size_t off = (size_t)ga * K + gk;
                vah  = *reinterpret_cast<const uint4*>(Ahi + off);
                valo = *reinterpret_cast<const uint4*>(Alo + off);
            }
            int gb = col0 + r;
            if (gb < N) {
                size_t off = (size_t)gb * K + gk;
                vbh  = *reinterpret_cast<const uint4*>(Bhi + off);
                vblo = *reinterpret_cast<const uint4*>(Blo + off);
            }
            *reinterpret_cast<uint4*>(&sAh[r][seg*8]) = vah;
            *reinterpret_cast<uint4*>(&sAl[r][seg*8]) = valo;
            *reinterpret_cast<uint4*>(&sBh[r][seg*8]) = vbh;
            *reinterpret_cast<uint4*>(&sBl[r][seg*8]) = vblo;
        }
        __syncthreads();

        #pragma unroll
        for (int kb = 0; kb < BK; kb += 16) {
            unsigned ah[2][4], al[2][4];
            #pragma unroll
            for (int i = 0; i < 2; i++) {
                int ar = wm*32 + i*16 + grp;
                int ac_ = kb + qid*2;
                ah[i][0] = *(const unsigned*)&sAh[ar  ][ac_  ];
                ah[i][1] = *(const unsigned*)&sAh[ar+8][ac_  ];
                ah[i][2] = *(const unsigned*)&sAh[ar  ][ac_+8];
                ah[i][3] = *(const unsigned*)&sAh[ar+8][ac_+8];
                al[i][0] = *(const unsigned*)&sAl[ar  ][ac_  ];
                al[i][1] = *(const unsigned*)&sAl[ar+8][ac_  ];
                al[i][2] = *(const unsigned*)&sAl[ar  ][ac_+8];
                al[i][3] = *(const unsigned*)&sAl[ar+8][ac_+8];
            }
            #pragma unroll
            for (int j = 0; j < 8; j++) {
                int nr  = wn*64 + j*8 + grp;
                int nc_ = kb + qid*2;
                unsigned bh0 = *(const unsigned*)&sBh[nr][nc_  ];
                unsigned bh1 = *(const unsigned*)&sBh[nr][nc_+8];
                unsigned bl0 = *(const unsigned*)&sBl[nr][nc_  ];
                unsigned bl1 = *(const unsigned*)&sBl[nr][nc_+8];
                #pragma unroll
                for (int i = 0; i < 2; i++) {
                    MMA_BF16(acc[i][j], ah[i], bh0, bh1);
                    MMA_BF16(acc[i][j], ah[i], bl0, bl1);
                    MMA_BF16(acc[i][j], al[i], bh0, bh1);
                }
            }
        }
        __syncthreads();
    }
}

// epilogue coordinate helpers (per thread)
#define EPI_ROW(i, r)  (wm*32 + (i)*16 + grp + ((r) >> 1)*8)
#define EPI_COL(j, r)  (wn*64 + (j)*8 + qid*2 + ((r) & 1))
#define EPI_DECLS                                          \
    const int lane = threadIdx.x & 31;                     \
    const int warp = threadIdx.x >> 5;                     \
    const int grp = lane >> 2, qid = lane & 3;             \
    const int wm = warp >> 1, wn = warp & 1;

// ---------------- fp32 -> (hi,lo) bf16 split --------------------------------
__global__ void k_split(const float* __restrict__ src,
                        unsigned short* __restrict__ hi,
                        unsigned short* __restrict__ lo, int n)
{
    int i = blockIdx.x * blockDim.x + threadIdx.x;
    if (i < n) split2(src[i], hi[i], lo[i]);
}

// ---------------- Q/K/V projection ------------------------------------------
__global__ void __launch_bounds__(256, 1)
k_qkv(const float* __restrict__ bu, const float* __restrict__ bv)
{
    const int z = blockIdx.z;
    bfp Whi = (bfp)(z == 0 ? g_Wqhi : (z == 1 ? g_Wkhi : g_Wvhi));
    bfp Wlo = (bfp)(z == 0 ? g_Wqlo : (z == 1 ? g_Wklo : g_Wvlo));
    const int row0 = blockIdx.y * 128, col0 = blockIdx.x * 128;
    float acc[2][8][4] = {};
    bmma_main((bfp)g_hshi, (bfp)g_hslo, MHS, Whi, Wlo, DD, DD, row0, col0, acc);
    EPI_DECLS
    #pragma unroll
    for (int i = 0; i < 2; i++)
        #pragma unroll
        for (int j = 0; j < 8; j++)
            #pragma unroll
            for (int r = 0; r < 4; r++) {
                int m = row0 + EPI_ROW(i, r);
                int n = col0 + EPI_COL(j, r);
                int b = m >> 10, t = m & 1023;
                int h = n >> 7,  d = n & 127;
                float v = acc[i][j][r];
                size_t idx = ((size_t)(b*HH + h)*TT + t)*DKK + d;
                if (z == 0) {
                    split2(v + bu[h*DKK + d], g_quhi[idx], g_qulo[idx]);
                    split2(v + bv[h*DKK + d], g_qvhi[idx], g_qvlo[idx]);
                } else if (z == 1) {
                    split2(v, g_khi[idx], g_klo[idx]);
                } else {
                    size_t it = ((size_t)(b*HH + h)*DKK + d)*TT + t;  // transposed
                    split2(v, g_vThi[it], g_vTlo[it]);
                }
            }
}

// ---------------- P projection ----------------------------------------------
__global__ void __launch_bounds__(256, 1) k_p()
{
    const int row0 = blockIdx.y * 128, col0 = blockIdx.x * 128;
    float acc[2][8][4] = {};
    bmma_main((bfp)g_pehi, (bfp)g_pelo, PP, (bfp)g_Wphi, (bfp)g_Wplo, DD,
              DD, row0, col0, acc);
    EPI_DECLS
    #pragma unroll
    for (int i = 0; i < 2; i++)
        #pragma unroll
        for (int j = 0; j < 8; j++)
            #pragma unroll
            for (int r = 0; r < 4; r++) {
                int m = row0 + EPI_ROW(i, r);
                if (m >= PP) continue;
                int n = col0 + EPI_COL(j, r);
                int h = n >> 7, d = n & 127;
                size_t idx = ((size_t)h*PP + m)*DKK + d;
                split2(acc[i][j][r], g_phi[idx], g_plo[idx]);
            }
}

// ---------------- AC: scores = qu @ k^T per (b,h) ---------------------------
__global__ void __launch_bounds__(256, 1) k_ac()
{
    const int bh = blockIdx.z;
    const size_t ob = (size_t)bh * TT * DKK;
    const int row0 = blockIdx.y * 128, col0 = blockIdx.x * 128;
    float acc[2][8][4] = {};
    bmma_main((bfp)(g_quhi + ob), (bfp)(g_qulo + ob), TT,
              (bfp)(g_khi + ob),  (bfp)(g_klo + ob),  TT,
              DKK, row0, col0, acc);
    EPI_DECLS
    float* C = g_scores + (size_t)bh * TT * TT;
    #pragma unroll
    for (int i = 0; i < 2; i++)
        #pragma unroll
        for (int j = 0; j < 8; j++)
            #pragma unroll
            for (int r = 0; r < 4; r++) {
                int m = row0 + EPI_ROW(i, r);
                int n = col0 + EPI_COL(j, r);
                C[(size_t)m * TT + n] = acc[i][j][r];
            }
}

// ---------------- BD: scores[m, n+m-1023] += qv @ p^T (rel-shift fused) -----
__global__ void __launch_bounds__(256, 1) k_bd()
{
    const int bh = blockIdx.z, h = bh & 7;
    const int row0 = blockIdx.y * 128, col0 = blockIdx.x * 128;
    if (row0 + col0 + 254 < 1023 || row0 + col0 > 2046) return; // no k in [0,T)
    const size_t oa = (size_t)bh * TT * DKK;
    const size_t op = (size_t)h * PP * DKK;
    float acc[2][8][4] = {};
    bmma_main((bfp)(g_qvhi + oa), (bfp)(g_qvlo + oa), TT,
              (bfp)(g_phi + op),  (bfp)(g_plo + op),  PP,
              DKK, row0, col0, acc);
    EPI_DECLS
    float* C = g_scores + (size_t)bh * TT * TT;
    #pragma unroll
    for (int i = 0; i < 2; i++)
        #pragma unroll
        for (int j = 0; j < 8; j++)
            #pragma unroll
            for (int r = 0; r < 4; r++) {
                int m = row0 + EPI_ROW(i, r);
                int n = col0 + EPI_COL(j, r);
                if (n < PP) {
                    int k = n + m - 1023;
                    if (k >= 0 && k < TT)
                        C[(size_t)m * TT + k] += acc[i][j][r];
                }
            }
}

// ---------------- softmax: fp32 scores -> attn hi/lo bf16 -------------------
__global__ void k_softmax()
{
    const size_t rowoff = (size_t)blockIdx.x * TT;
    const float* r = g_scores + rowoff;
    const int tid = threadIdx.x;                 // 256 threads, float4 each
    float4 v = reinterpret_cast<const float4*>(r)[tid];
    const float s = 0.08838834764831845f;        // 1/sqrt(128)
    v.x *= s; v.y *= s; v.z *= s; v.w *= s;

    __shared__ float redm[8];
    __shared__ float reds[8];

    float m = fmaxf(fmaxf(v.x, v.y), fmaxf(v.z, v.w));
    #pragma unroll
    for (int o = 16; o > 0; o >>= 1) m = fmaxf(m, __shfl_xor_sync(~0u, m, o));
    if ((tid & 31) == 0) redm[tid >> 5] = m;
    __syncthreads();
    m = redm[0];
    #pragma unroll
    for (int w = 1; w < 8; w++) m = fmaxf(m, redm[w]);

    float4 e;
    e.x = __expf(v.x - m); e.y = __expf(v.y - m);
    e.z = __expf(v.z - m); e.w = __expf(v.w - m);
    float sum = e.x + e.y + e.z + e.w;
    #pragma unroll
    for (int o = 16; o > 0; o >>= 1) sum += __shfl_xor_sync(~0u, sum, o);
    if ((tid & 31) == 0) reds[tid >> 5] = sum;
    __syncthreads();
    sum = reds[0];
    #pragma unroll
    for (int w = 1; w < 8; w++) sum += reds[w];

    float inv = __frcp_rn(sum);
    float p0 = e.x*inv, p1 = e.y*inv, p2 = e.z*inv, p3 = e.w*inv;
    unsigned short h0,h1,h2,h3, l0,l1,l2,l3;
    split2(p0,h0,l0); split2(p1,h1,l1); split2(p2,h2,l2); split2(p3,h3,l3);
    size_t base = rowoff + (size_t)tid*4;
    uint2 ph = make_uint2((unsigned)h0 | ((unsigned)h1 << 16),
                          (unsigned)h2 | ((unsigned)h3 << 16));
    uint2 pl = make_uint2((unsigned)l0 | ((unsigned)l1 << 16),
                          (unsigned)l2 | ((unsigned)l3 << 16));
    *reinterpret_cast<uint2*>(&g_athi[base]) = ph;
    *reinterpret_cast<uint2*>(&g_atlo[base]) = pl;
}

// ---------------- AV: o = attn @ v per (b,h) (B = v^T, NT form) -------------
__global__ void __launch_bounds__(256, 1) k_av()
{
    const int bh = blockIdx.z, b = bh >> 3, h = bh & 7;
    const size_t oa = (size_t)bh * TT * TT;
    const size_t ov = (size_t)bh * DKK * TT;
    const int row0 = blockIdx.y * 128, col0 = 0;  // N = 128 fits one tile
    float acc[2][8][4] = {};
    bmma_main((bfp)(g_athi + oa), (bfp)(g_atlo + oa), TT,
              (bfp)(g_vThi + ov), (bfp)(g_vTlo + ov), DKK,
              TT, row0, col0, acc);
    EPI_DECLS
    #pragma unroll
    for (int i = 0; i < 2; i++)
        #pragma unroll
        for (int j = 0; j < 8; j++)
            #pragma unroll
            for (int r = 0; r < 4; r++) {
                int m = row0 + EPI_ROW(i, r);
                int n = EPI_COL(j, r);              // head-dim 0..127
                size_t idx = ((size_t)(b*TT + m)*HH + h)*DKK + n; // (b,t,h,d)
                split2(acc[i][j][r], g_ohi[idx], g_olo[idx]);
            }
}

// ---------------- output projection -----------------------------------------
__global__ void __launch_bounds__(256, 1) k_out(float* __restrict__ out)
{
    const int row0 = blockIdx.y * 128, col0 = blockIdx.x * 128;
    float acc[2][8][4] = {};
    bmma_main((bfp)g_ohi, (bfp)g_olo, MHS, (bfp)g_Wohi, (bfp)g_Wolo, DD,
              DD, row0, col0, acc);
    EPI_DECLS
    #pragma unroll
    for (int i = 0; i < 2; i++)
        #pragma unroll
        for (int j = 0; j < 8; j++)
            #pragma unroll
            for (int r = 0; r < 4; r++) {
                int m = row0 + EPI_ROW(i, r);
                int n = col0 + EPI_COL(j, r);
                out[(size_t)m * DD + n] = acc[i][j][r];
            }
}

// ---------------- launch ----------------------------------------------------
extern "C" void kernel_launch(void* const* d_in, const int* in_sizes, int n_in,
                              void* d_out, int out_size)
{
    const float* hs = (const float*)d_in[0];
    const float* pe = (const float*)d_in[1];
    const float* Wq = (const float*)d_in[2];
    const float* Wk = (const float*)d_in[3];
    const float* Wv = (const float*)d_in[4];
    const float* Wo = (const float*)d_in[5];
    const float* Wp = (const float*)d_in[6];
    const float* bu = (const float*)d_in[7];
    const float* bv = (const float*)d_in[8];
    float* out = (float*)d_out;

    unsigned short *hshi, *hslo, *pehi, *pelo;
    unsigned short *wqh, *wql, *wkh, *wkl, *wvh, *wvl, *woh, *wol, *wph, *wpl;
    cudaGetSymbolAddress((void**)&hshi, g_hshi); cudaGetSymbolAddress((void**)&hslo, g_hslo);
    cudaGetSymbolAddress((void**)&pehi, g_pehi); cudaGetSymbolAddress((void**)&pelo, g_pelo);
    cudaGetSymbolAddress((void**)&wqh, g_Wqhi);  cudaGetSymbolAddress((void**)&wql, g_Wqlo);
    cudaGetSymbolAddress((void**)&wkh, g_Wkhi);  cudaGetSymbolAddress((void**)&wkl, g_Wklo);
    cudaGetSymbolAddress((void**)&wvh, g_Wvhi);  cudaGetSymbolAddress((void**)&wvl, g_Wvlo);
    cudaGetSymbolAddress((void**)&woh, g_Wohi);  cudaGetSymbolAddress((void**)&wol, g_Wolo);
    cudaGetSymbolAddress((void**)&wph, g_Wphi);  cudaGetSymbolAddress((void**)&wpl, g_Wplo);

    k_split<<<(MHS*DD + 255)/256, 256>>>(hs, hshi, hslo, MHS*DD);
    k_split<<<(PP*DD + 255)/256, 256>>>(pe, pehi, pelo, PP*DD);
    k_split<<<(DD*DD + 255)/256, 256>>>(Wq, wqh, wql, DD*DD);
    k_split<<<(DD*DD + 255)/256, 256>>>(Wk, wkh, wkl, DD*DD);
    k_split<<<(DD*DD + 255)/256, 256>>>(Wv, wvh, wvl, DD*DD);
    k_split<<<(DD*DD + 255)/256, 256>>>(Wo, woh, wol, DD*DD);
    k_split<<<(DD*DD + 255)/256, 256>>>(Wp, wph, wpl, DD*DD);

    k_qkv<<<dim3(8, 32, 3), 256>>>(bu, bv);
    k_p  <<<dim3(8, 16), 256>>>();
    k_ac <<<dim3(8, 8, BATCH*HH), 256>>>();
    k_bd <<<dim3(16, 8, BATCH*HH), 256>>>();
    k_softmax<<<BATCH*HH*TT, 256>>>();
    k_av <<<dim3(1, 8, BATCH*HH), 256>>>();
    k_out<<<dim3(8, 32), 256>>>(out);
}